// round 10
// baseline (speedup 1.0000x reference)
#include <cuda_runtime.h>
#include <cuda_fp16.h>
#include <cstdint>

#define N_NODES  20000
#define KN       32
#define CIN      512
#define COUT     512
#define KTOT     1024

#define BM       32
#define NBLK     (N_NODES / BM)      // 625 CTAs, one stripe each

#define AH       1032                // A row stride (halves); 2064B -> 16B-aligned, ldmatrix conflict-free
#define ABUF_H   (BM * AH)           // 33024 halves
#define BH2      24                  // B row stride (halves); 48B -> 16B-aligned, conflict-free
#define BSTG_H   (COUT * BH2)        // 12288 halves per k16 stage
#define NSTAGE   4
#define NKT      64                  // K steps of 16 halves

__device__ __half g_Wh[(size_t)COUT * KTOT];
__device__ float  g_bias[COUT];

// ---------------------------------------------------------------------------
// Kernel 0: W -> fp16 concat layout, bias sum
// ---------------------------------------------------------------------------
__global__ void __launch_bounds__(256) convert_kernel(
    const float* __restrict__ Wl, const float* __restrict__ bl,
    const float* __restrict__ Wr, const float* __restrict__ br)
{
    const int n = blockIdx.x;
    const int t = threadIdx.x;
    const int k = t * 4;
    const float* src = (k < CIN) ? (Wl + (size_t)n * CIN + k)
                                 : (Wr + (size_t)n * CIN + (k - CIN));
    float4 v = *reinterpret_cast<const float4*>(src);
    __half2* dst = reinterpret_cast<__half2*>(&g_Wh[(size_t)n * KTOT + k]);
    dst[0] = __floats2half2_rn(v.x, v.y);
    dst[1] = __floats2half2_rn(v.z, v.w);
    if (n == 0)
        for (int c = t; c < COUT; c += 256) g_bias[c] = bl[c] + br[c];
}

// ---------------------------------------------------------------------------
// PTX helpers
// ---------------------------------------------------------------------------
__device__ __forceinline__ void cp_async16_s(uint32_t saddr, const void* g) {
    asm volatile("cp.async.cg.shared.global [%0], [%1], 16;" :: "r"(saddr), "l"(g));
}
__device__ __forceinline__ void cp_commit() {
    asm volatile("cp.async.commit_group;");
}
template <int NW>
__device__ __forceinline__ void cp_wait() {
    asm volatile("cp.async.wait_group %0;" :: "n"(NW));
}
__device__ __forceinline__ void ldsm_x4(uint32_t r[4], uint32_t saddr) {
    asm volatile("ldmatrix.sync.aligned.m8n8.x4.shared.b16 {%0,%1,%2,%3}, [%4];"
                 : "=r"(r[0]), "=r"(r[1]), "=r"(r[2]), "=r"(r[3]) : "r"(saddr));
}
__device__ __forceinline__ void mma_f16(float c[4], const uint32_t a[4],
                                        uint32_t b0, uint32_t b1) {
    asm volatile(
        "mma.sync.aligned.m16n8k16.row.col.f32.f16.f16.f32 "
        "{%0,%1,%2,%3}, {%4,%5,%6,%7}, {%8,%9}, {%0,%1,%2,%3};\n"
        : "+f"(c[0]), "+f"(c[1]), "+f"(c[2]), "+f"(c[3])
        : "r"(a[0]), "r"(a[1]), "r"(a[2]), "r"(a[3]), "r"(b0), "r"(b1));
}
__device__ __forceinline__ uint32_t h2u(__half2 h) {
    return *reinterpret_cast<uint32_t*>(&h);
}

// ---------------------------------------------------------------------------
// One stripe per CTA: fill A (all 32 warps) -> barrier -> GEMM (all 32 warps)
// ---------------------------------------------------------------------------
__global__ void __launch_bounds__(1024, 1) fused_kernel(
    const float* __restrict__ x,
    const float* __restrict__ neigh,
    float* __restrict__ out)
{
    extern __shared__ __half sm[];
    __half* Abuf = sm;                      // [BM][AH]
    __half* Bbuf = sm + ABUF_H;             // [NSTAGE][COUT][BH2]

    const int tid  = threadIdx.x;
    const int lane = tid & 31;
    const int w    = tid >> 5;              // 0..31, warp -> 16 output cols
    const int m0   = blockIdx.x * BM;

    // ================= Phase 1: fill A (32 rows x [x | mean(neigh)]) =========
    // 1a: x rows (4096 float4 tasks, 4 per thread)
#pragma unroll
    for (int i = 0; i < 4; i++) {
        const int idx = tid + i * 1024;
        const int r   = idx >> 7;
        const int c4  = idx & 127;
        float4 v = __ldg(reinterpret_cast<const float4*>(x)
                         + (size_t)(m0 + r) * (CIN / 4) + c4);
        *reinterpret_cast<uint2*>(Abuf + r * AH + c4 * 4) =
            make_uint2(h2u(__floats2half2_rn(v.x, v.y)),
                       h2u(__floats2half2_rn(v.z, v.w)));
    }
    // 1b: mean over KN neighbors (4096 tasks, 4 per thread)
#pragma unroll
    for (int i = 0; i < 4; i++) {
        const int idx = tid + i * 1024;
        const int r   = idx >> 7;
        const int c4  = idx & 127;
        const float4* base = reinterpret_cast<const float4*>(neigh)
                             + (size_t)(m0 + r) * KN * (CIN / 4) + c4;
        float sx = 0.f, sy = 0.f, sz = 0.f, sw = 0.f;
#pragma unroll 8
        for (int k = 0; k < KN; k++) {
            float4 v = __ldg(base + (size_t)k * (CIN / 4));
            sx += v.x; sy += v.y; sz += v.z; sw += v.w;
        }
        const float inv = 1.0f / (float)KN;
        *reinterpret_cast<uint2*>(Abuf + r * AH + CIN + c4 * 4) =
            make_uint2(h2u(__floats2half2_rn(sx * inv, sy * inv)),
                       h2u(__floats2half2_rn(sz * inv, sw * inv)));
    }
    __syncthreads();

    // ================= Phase 2: GEMM, warp w -> cols [w*16, w*16+16) ==========
    const uint32_t Abase = (uint32_t)__cvta_generic_to_shared(Abuf);
    const uint32_t Bbase = (uint32_t)__cvta_generic_to_shared(Bbuf);
    const uint32_t a_lane = (uint32_t)(((lane & 15) * AH + (lane >> 4) * 8) * 2);
    const uint32_t b_lane = (uint32_t)(((w * 16 + ((lane >> 4) << 3) + (lane & 7)) * BH2
                                        + ((lane >> 3) & 1) * 8) * 2);
    const int g = lane >> 2, t4 = lane & 3;

    float acc[2][2][4];
#pragma unroll
    for (int mt = 0; mt < 2; mt++)
#pragma unroll
        for (int nt = 0; nt < 2; nt++)
#pragma unroll
            for (int q = 0; q < 4; q++) acc[mt][nt][q] = 0.f;

    // per-warp-private B k16 stage: 16 rows x 32B = 32 lanes x 16B
    auto issueB = [&](int kt) {
        const uint32_t dpar = (uint32_t)((kt & (NSTAGE - 1)) * BSTG_H * 2);
        const int r   = w * 16 + (lane >> 1);
        const int seg = lane & 1;
        cp_async16_s(Bbase + dpar + (uint32_t)((r * BH2 + seg * 8) * 2),
                     g_Wh + (size_t)r * KTOT + kt * 16 + seg * 8);
        cp_commit();
    };

    issueB(0); issueB(1); issueB(2);
#pragma unroll 1
    for (int kt = 0; kt < NKT; kt++) {
        cp_wait<2>();                        // stage kt resident
        if (kt + 3 < NKT) issueB(kt + 3);
        else              cp_commit();       // keep group-count invariant

        const uint32_t apar = Abase + a_lane + (uint32_t)(kt * 32);
        const uint32_t bpar = Bbase + (uint32_t)((kt & (NSTAGE - 1)) * BSTG_H * 2) + b_lane;

        uint32_t a0[4], a1[4], b[4];
        ldsm_x4(a0, apar);
        ldsm_x4(a1, apar + 16 * AH * 2);
        ldsm_x4(b,  bpar);
        mma_f16(acc[0][0], a0, b[0], b[1]);
        mma_f16(acc[1][0], a1, b[0], b[1]);
        mma_f16(acc[0][1], a0, b[2], b[3]);
        mma_f16(acc[1][1], a1, b[2], b[3]);
    }

    // ================= Epilogue =================
#pragma unroll
    for (int mt = 0; mt < 2; mt++)
#pragma unroll
        for (int nt = 0; nt < 2; nt++) {
            const int col = w * 16 + nt * 8 + 2 * t4;
            const int row = m0 + mt * 16 + g;
            const float b0v = __ldg(&g_bias[col]);
            const float b1v = __ldg(&g_bias[col + 1]);
            *reinterpret_cast<float2*>(&out[(size_t)row * COUT + col]) =
                make_float2(acc[mt][nt][0] + b0v, acc[mt][nt][1] + b1v);
            *reinterpret_cast<float2*>(&out[(size_t)(row + 8) * COUT + col]) =
                make_float2(acc[mt][nt][2] + b0v, acc[mt][nt][3] + b1v);
        }
}

// ---------------------------------------------------------------------------
extern "C" void kernel_launch(void* const* d_in, const int* in_sizes, int n_in,
                              void* d_out, int out_size) {
    const float* x  = (const float*)d_in[0];
    const float* nx = (const float*)d_in[1];
    const float* Wl = (const float*)d_in[2];
    const float* bl = (const float*)d_in[3];
    const float* Wr = (const float*)d_in[4];
    const float* br = (const float*)d_in[5];
    float* out = (float*)d_out;

    convert_kernel<<<COUT, 256>>>(Wl, bl, Wr, br);

    const int smem_bytes = (ABUF_H + NSTAGE * BSTG_H) * (int)sizeof(__half); // 164352
    cudaFuncSetAttribute(fused_kernel,
                         cudaFuncAttributeMaxDynamicSharedMemorySize, smem_bytes);
    fused_kernel<<<NBLK, 1024, smem_bytes>>>(x, nx, out);
}

// round 11
// speedup vs baseline: 1.1901x; 1.1901x over previous
#include <cuda_runtime.h>
#include <cuda_fp16.h>
#include <cstdint>

#define N_NODES 20000
#define KN      32
#define CIN     512
#define COUT    512
#define KTOT    1024

// GEMM tiling
#define TM      128
#define TN      128
#define TKH     64                   // halves of K per stage
#define NKT     (KTOT / TKH)         // 16
#define NST     3                    // pipeline stages
#define SH      72                   // smem row stride (halves): 144B, 16B-aligned, %128=16 -> conflict-free
#define STG_H   (TM * SH)            // 9216 halves per operand stage

__device__ __half g_Wh[(size_t)COUT * KTOT];     // [col][k] concat(Wl,Wr), fp16
__device__ __half g_xh[(size_t)N_NODES * CIN];   // x, fp16
__device__ __half g_aggh[(size_t)N_NODES * CIN]; // mean(neigh), fp16
__device__ float  g_bias[COUT];

// ---------------------------------------------------------------------------
// Kernel 0: W -> fp16 concat layout, bias sum
// ---------------------------------------------------------------------------
__global__ void __launch_bounds__(256) convert_kernel(
    const float* __restrict__ Wl, const float* __restrict__ bl,
    const float* __restrict__ Wr, const float* __restrict__ br)
{
    const int n = blockIdx.x;
    const int t = threadIdx.x;
    const int k = t * 4;
    const float* src = (k < CIN) ? (Wl + (size_t)n * CIN + k)
                                 : (Wr + (size_t)n * CIN + (k - CIN));
    float4 v = *reinterpret_cast<const float4*>(src);
    __half2* dst = reinterpret_cast<__half2*>(&g_Wh[(size_t)n * KTOT + k]);
    dst[0] = __floats2half2_rn(v.x, v.y);
    dst[1] = __floats2half2_rn(v.z, v.w);
    if (n == 0)
        for (int c = t; c < COUT; c += 256) g_bias[c] = bl[c] + br[c];
}

// ---------------------------------------------------------------------------
// Kernel 1: per-node mean(neigh) -> fp16, and x -> fp16  (pure DRAM streaming,
// R1-proven config: 128 threads, one node per block, 2048 thr/SM)
// ---------------------------------------------------------------------------
__device__ __forceinline__ uint32_t h2u(__half2 h) {
    return *reinterpret_cast<uint32_t*>(&h);
}

__global__ void __launch_bounds__(128) agg_kernel(const float* __restrict__ x,
                                                  const float* __restrict__ neigh)
{
    const int n  = blockIdx.x;
    const int c4 = threadIdx.x;                       // 0..127
    // x convert
    float4 xv = __ldg(reinterpret_cast<const float4*>(x) + (size_t)n * (CIN / 4) + c4);
    *reinterpret_cast<uint2*>(&g_xh[(size_t)n * CIN + c4 * 4]) =
        make_uint2(h2u(__floats2half2_rn(xv.x, xv.y)),
                   h2u(__floats2half2_rn(xv.z, xv.w)));
    // neighbor mean
    const float4* base = reinterpret_cast<const float4*>(neigh)
                         + (size_t)n * (KN * CIN / 4) + c4;
    float sx = 0.f, sy = 0.f, sz = 0.f, sw = 0.f;
#pragma unroll 8
    for (int k = 0; k < KN; k++) {
        float4 v = __ldg(&base[(size_t)k * (CIN / 4)]);
        sx += v.x; sy += v.y; sz += v.z; sw += v.w;
    }
    const float inv = 1.0f / (float)KN;
    *reinterpret_cast<uint2*>(&g_aggh[(size_t)n * CIN + c4 * 4]) =
        make_uint2(h2u(__floats2half2_rn(sx * inv, sy * inv)),
                   h2u(__floats2half2_rn(sz * inv, sw * inv)));
}

// ---------------------------------------------------------------------------
// PTX helpers
// ---------------------------------------------------------------------------
__device__ __forceinline__ void cp_async16_s(uint32_t saddr, const void* g) {
    asm volatile("cp.async.cg.shared.global [%0], [%1], 16;" :: "r"(saddr), "l"(g));
}
__device__ __forceinline__ void cp_commit() {
    asm volatile("cp.async.commit_group;");
}
template <int NW>
__device__ __forceinline__ void cp_wait() {
    asm volatile("cp.async.wait_group %0;" :: "n"(NW));
}
__device__ __forceinline__ void ldsm_x4(uint32_t r[4], uint32_t saddr) {
    asm volatile("ldmatrix.sync.aligned.m8n8.x4.shared.b16 {%0,%1,%2,%3}, [%4];"
                 : "=r"(r[0]), "=r"(r[1]), "=r"(r[2]), "=r"(r[3]) : "r"(saddr));
}
__device__ __forceinline__ void mma_f16(float c[4], const uint32_t a[4],
                                        uint32_t b0, uint32_t b1) {
    asm volatile(
        "mma.sync.aligned.m16n8k16.row.col.f32.f16.f16.f32 "
        "{%0,%1,%2,%3}, {%4,%5,%6,%7}, {%8,%9}, {%0,%1,%2,%3};\n"
        : "+f"(c[0]), "+f"(c[1]), "+f"(c[2]), "+f"(c[3])
        : "r"(a[0]), "r"(a[1]), "r"(a[2]), "r"(a[3]), "r"(b0), "r"(b1));
}

// ---------------------------------------------------------------------------
// Kernel 2: out = [xh|aggh] @ Wh^T + bias.  128x128 tiles, 3-stage pipeline.
// ---------------------------------------------------------------------------
__global__ void __launch_bounds__(256, 2) gemm_kernel(float* __restrict__ out)
{
    extern __shared__ __half sm[];
    __half* As = sm;                 // [NST][TM][SH]
    __half* Bs = sm + NST * STG_H;   // [NST][TN][SH]

    const int tid  = threadIdx.x;
    const int lane = tid & 31;
    const int warp = tid >> 5;                  // 0..7
    const int warpM = (warp & 3) * 32;
    const int warpN = (warp >> 2) * 64;
    const int m0 = blockIdx.x * TM;
    const int n0 = blockIdx.y * TN;

    const uint32_t Abase = (uint32_t)__cvta_generic_to_shared(As);
    const uint32_t Bbase = (uint32_t)__cvta_generic_to_shared(Bs);
    const uint32_t a_lane = (uint32_t)(((lane & 15) * SH + (lane >> 4) * 8) * 2);
    const uint32_t b_lane = (uint32_t)((((lane & 7) + ((lane >> 4) << 3)) * SH
                                        + ((lane >> 3) & 1) * 8) * 2);

    // stage loader: A from g_xh (k<512) or g_aggh, B from g_Wh. 1024 segs each.
    auto issue_stage = [&](int kt) {
        const int slot = kt % NST;
        const int kb   = kt * TKH;
        const __half* Asrc = (kb < CIN) ? g_xh : g_aggh;
        const int ka = (kb < CIN) ? kb : (kb - CIN);
#pragma unroll
        for (int i = 0; i < 4; i++) {
            const int idx = tid + i * 256;      // 0..1023
            const int r   = idx >> 3;           // 0..127
            const int seg = idx & 7;            // 0..7
            int ar = m0 + r; if (ar > N_NODES - 1) ar = N_NODES - 1;
            cp_async16_s(Abase + (uint32_t)((slot * STG_H + r * SH + seg * 8) * 2),
                         Asrc + (size_t)ar * CIN + ka + seg * 8);
            cp_async16_s(Bbase + (uint32_t)((slot * STG_H + r * SH + seg * 8) * 2),
                         g_Wh + (size_t)(n0 + r) * KTOT + kb + seg * 8);
        }
        cp_commit();
    };

    float acc[2][8][4];
#pragma unroll
    for (int mt = 0; mt < 2; mt++)
#pragma unroll
        for (int nt = 0; nt < 8; nt++)
#pragma unroll
            for (int q = 0; q < 4; q++) acc[mt][nt][q] = 0.f;

    issue_stage(0);
    issue_stage(1);

#pragma unroll 1
    for (int kt = 0; kt < NKT; kt++) {
        cp_wait<1>();                 // stage kt resident (kt+1 may be in flight)
        __syncthreads();              // all warps see it; prior stage fully consumed
        if (kt + 2 < NKT) issue_stage(kt + 2);

        const uint32_t Asl = Abase + (uint32_t)((kt % NST) * STG_H * 2);
        const uint32_t Bsl = Bbase + (uint32_t)((kt % NST) * STG_H * 2);
#pragma unroll
        for (int ks = 0; ks < 4; ks++) {
            const uint32_t ko = (uint32_t)(ks * 16 * 2);
            uint32_t a0[4], a1[4];
            ldsm_x4(a0, Asl + a_lane + ko + (uint32_t)(warpM * SH * 2));
            ldsm_x4(a1, Asl + a_lane + ko + (uint32_t)((warpM + 16) * SH * 2));
#pragma unroll
            for (int p = 0; p < 4; p++) {
                uint32_t b[4];
                ldsm_x4(b, Bsl + b_lane + ko + (uint32_t)((warpN + p * 16) * SH * 2));
                mma_f16(acc[0][2 * p],     a0, b[0], b[1]);
                mma_f16(acc[1][2 * p],     a1, b[0], b[1]);
                mma_f16(acc[0][2 * p + 1], a0, b[2], b[3]);
                mma_f16(acc[1][2 * p + 1], a1, b[2], b[3]);
            }
        }
    }

    // epilogue
    const int g = lane >> 2, t4 = lane & 3;
#pragma unroll
    for (int mt = 0; mt < 2; mt++)
#pragma unroll
        for (int nt = 0; nt < 8; nt++) {
            const int col = n0 + warpN + nt * 8 + 2 * t4;
            const float b0v = __ldg(&g_bias[col]);
            const float b1v = __ldg(&g_bias[col + 1]);
            const int row0 = m0 + warpM + mt * 16 + g;
            if (row0 < N_NODES)
                *reinterpret_cast<float2*>(&out[(size_t)row0 * COUT + col]) =
                    make_float2(acc[mt][nt][0] + b0v, acc[mt][nt][1] + b1v);
            const int row1 = row0 + 8;
            if (row1 < N_NODES)
                *reinterpret_cast<float2*>(&out[(size_t)row1 * COUT + col]) =
                    make_float2(acc[mt][nt][2] + b0v, acc[mt][nt][3] + b1v);
        }
}

// ---------------------------------------------------------------------------
extern "C" void kernel_launch(void* const* d_in, const int* in_sizes, int n_in,
                              void* d_out, int out_size) {
    const float* x  = (const float*)d_in[0];
    const float* nx = (const float*)d_in[1];
    const float* Wl = (const float*)d_in[2];
    const float* bl = (const float*)d_in[3];
    const float* Wr = (const float*)d_in[4];
    const float* br = (const float*)d_in[5];
    float* out = (float*)d_out;

    convert_kernel<<<COUT, 256>>>(Wl, bl, Wr, br);
    agg_kernel<<<N_NODES, 128>>>(x, nx);

    const int smem_bytes = NST * 2 * STG_H * (int)sizeof(__half);  // 110592
    cudaFuncSetAttribute(gemm_kernel,
                         cudaFuncAttributeMaxDynamicSharedMemorySize, smem_bytes);
    dim3 grid((N_NODES + TM - 1) / TM, COUT / TN);                 // 157 x 4
    gemm_kernel<<<grid, 256, smem_bytes>>>(out);
}

// round 13
// speedup vs baseline: 1.2053x; 1.0128x over previous
#include <cuda_runtime.h>
#include <cuda_fp16.h>
#include <cstdint>

#define N_NODES 20000
#define KN      32
#define CIN     512
#define COUT    512
#define KTOT    1024

// GEMM tiling
#define TM      128
#define TN      128
#define TKH     64                   // halves of K per stage
#define NKT     (KTOT / TKH)         // 16
#define NST     3                    // pipeline stages
#define SH      72                   // smem row stride (halves): 144B, 16B-aligned, conflict-free
#define STG_H   (TM * SH)            // 9216 halves per operand stage

#define XCONV_BLKS  2048
#define XCONV_TASKS 1250             // float4 tasks per x-convert block (2048*1250 = 20000*128)

__device__ __half g_Wh[(size_t)COUT * KTOT];     // [col][k] concat(Wl,Wr), fp16
__device__ __half g_xh[(size_t)N_NODES * CIN];   // x, fp16
__device__ __half g_aggh[(size_t)N_NODES * CIN]; // mean(neigh), fp16
__device__ float  g_bias[COUT];

__device__ __forceinline__ uint32_t h2u(__half2 h) {
    return *reinterpret_cast<uint32_t*>(&h);
}

// ---------------------------------------------------------------------------
// Kernel 0: W -> fp16 concat layout, bias sum, AND x -> fp16
// (x-convert lives here so the PDL-overlapped gemm can read xh safely:
//  this kernel is fully serialized before agg starts.)
// ---------------------------------------------------------------------------
__global__ void __launch_bounds__(256) convert_kernel(
    const float* __restrict__ x,
    const float* __restrict__ Wl, const float* __restrict__ bl,
    const float* __restrict__ Wr, const float* __restrict__ br)
{
    const int b = blockIdx.x;
    const int t = threadIdx.x;
    if (b < COUT) {
        const int k = t * 4;
        const float* src = (k < CIN) ? (Wl + (size_t)b * CIN + k)
                                     : (Wr + (size_t)b * CIN + (k - CIN));
        float4 v = *reinterpret_cast<const float4*>(src);
        __half2* dst = reinterpret_cast<__half2*>(&g_Wh[(size_t)b * KTOT + k]);
        dst[0] = __floats2half2_rn(v.x, v.y);
        dst[1] = __floats2half2_rn(v.z, v.w);
        if (b == 0)
            for (int c = t; c < COUT; c += 256) g_bias[c] = bl[c] + br[c];
    } else {
        const int start = (b - COUT) * XCONV_TASKS;
        const int end   = start + XCONV_TASKS;
        for (int i = start + t; i < end; i += 256) {
            float4 v = __ldg(reinterpret_cast<const float4*>(x) + i);
            *reinterpret_cast<uint2*>(&g_xh[(size_t)i * 4]) =
                make_uint2(h2u(__floats2half2_rn(v.x, v.y)),
                           h2u(__floats2half2_rn(v.z, v.w)));
        }
    }
}

// ---------------------------------------------------------------------------
// Kernel 1: per-node mean(neigh) -> fp16  (pure DRAM streamer, R1-proven cfg)
// ---------------------------------------------------------------------------
__global__ void __launch_bounds__(128) agg_kernel(const float* __restrict__ neigh)
{
    const int n  = blockIdx.x;
    const int c4 = threadIdx.x;                       // 0..127
    const float4* base = reinterpret_cast<const float4*>(neigh)
                         + (size_t)n * (KN * CIN / 4) + c4;
    float sx = 0.f, sy = 0.f, sz = 0.f, sw = 0.f;
#pragma unroll 8
    for (int k = 0; k < KN; k++) {
        float4 v = __ldg(&base[(size_t)k * (CIN / 4)]);
        sx += v.x; sy += v.y; sz += v.z; sw += v.w;
    }
    const float inv = 1.0f / (float)KN;
    *reinterpret_cast<uint2*>(&g_aggh[(size_t)n * CIN + c4 * 4]) =
        make_uint2(h2u(__floats2half2_rn(sx * inv, sy * inv)),
                   h2u(__floats2half2_rn(sz * inv, sw * inv)));
}

// ---------------------------------------------------------------------------
// PTX helpers
// ---------------------------------------------------------------------------
__device__ __forceinline__ void cp_async16_s(uint32_t saddr, const void* g) {
    asm volatile("cp.async.cg.shared.global [%0], [%1], 16;" :: "r"(saddr), "l"(g));
}
__device__ __forceinline__ void cp_commit() {
    asm volatile("cp.async.commit_group;");
}
template <int NW>
__device__ __forceinline__ void cp_wait() {
    asm volatile("cp.async.wait_group %0;" :: "n"(NW));
}
__device__ __forceinline__ void ldsm_x4(uint32_t r[4], uint32_t saddr) {
    asm volatile("ldmatrix.sync.aligned.m8n8.x4.shared.b16 {%0,%1,%2,%3}, [%4];"
                 : "=r"(r[0]), "=r"(r[1]), "=r"(r[2]), "=r"(r[3]) : "r"(saddr));
}
__device__ __forceinline__ void mma_f16(float c[4], const uint32_t a[4],
                                        uint32_t b0, uint32_t b1) {
    asm volatile(
        "mma.sync.aligned.m16n8k16.row.col.f32.f16.f16.f32 "
        "{%0,%1,%2,%3}, {%4,%5,%6,%7}, {%8,%9}, {%0,%1,%2,%3};\n"
        : "+f"(c[0]), "+f"(c[1]), "+f"(c[2]), "+f"(c[3])
        : "r"(a[0]), "r"(a[1]), "r"(a[2]), "r"(a[3]), "r"(b0), "r"(b1));
}

// ---------------------------------------------------------------------------
// Kernel 2: out = [xh|aggh] @ Wh^T + bias.  128x128 tiles, 3-stage pipeline.
// PDL: chunks 0..7 read xh (ready before agg); sync before touching aggh.
// ---------------------------------------------------------------------------
__global__ void __launch_bounds__(256, 2) gemm_kernel(float* __restrict__ out)
{
    extern __shared__ __half sm[];
    __half* As = sm;                 // [NST][TM][SH]
    __half* Bs = sm + NST * STG_H;   // [NST][TN][SH]

    const int tid  = threadIdx.x;
    const int lane = tid & 31;
    const int warp = tid >> 5;                  // 0..7
    const int warpM = (warp & 3) * 32;
    const int warpN = (warp >> 2) * 64;
    const int m0 = blockIdx.x * TM;
    const int n0 = blockIdx.y * TN;

    const uint32_t Abase = (uint32_t)__cvta_generic_to_shared(As);
    const uint32_t Bbase = (uint32_t)__cvta_generic_to_shared(Bs);
    const uint32_t a_lane = (uint32_t)(((lane & 15) * SH + (lane >> 4) * 8) * 2);
    const uint32_t b_lane = (uint32_t)((((lane & 7) + ((lane >> 4) << 3)) * SH
                                        + ((lane >> 3) & 1) * 8) * 2);

    auto issue_stage = [&](int kt) {
        const int slot = kt % NST;
        const int kb   = kt * TKH;
        const __half* Asrc = (kb < CIN) ? g_xh : g_aggh;
        const int ka = (kb < CIN) ? kb : (kb - CIN);
#pragma unroll
        for (int i = 0; i < 4; i++) {
            const int idx = tid + i * 256;      // 0..1023
            const int r   = idx >> 3;           // 0..127
            const int seg = idx & 7;            // 0..7
            int ar = m0 + r; if (ar > N_NODES - 1) ar = N_NODES - 1;
            cp_async16_s(Abase + (uint32_t)((slot * STG_H + r * SH + seg * 8) * 2),
                         Asrc + (size_t)ar * CIN + ka + seg * 8);
            cp_async16_s(Bbase + (uint32_t)((slot * STG_H + r * SH + seg * 8) * 2),
                         g_Wh + (size_t)(n0 + r) * KTOT + kb + seg * 8);
        }
        cp_commit();
    };

    float acc[2][8][4];
#pragma unroll
    for (int mt = 0; mt < 2; mt++)
#pragma unroll
        for (int nt = 0; nt < 8; nt++)
#pragma unroll
            for (int q = 0; q < 4; q++) acc[mt][nt][q] = 0.f;

    issue_stage(0);
    issue_stage(1);

#pragma unroll 1
    for (int kt = 0; kt < NKT; kt++) {
        cp_wait<1>();
        __syncthreads();
        // first prefetch that touches aggh is chunk 8 (kb=512): wait for agg.
        if (kt + 2 == CIN / TKH) cudaGridDependencySynchronize();
        if (kt + 2 < NKT) issue_stage(kt + 2);

        const uint32_t Asl = Abase + (uint32_t)((kt % NST) * STG_H * 2);
        const uint32_t Bsl = Bbase + (uint32_t)((kt % NST) * STG_H * 2);
#pragma unroll
        for (int ks = 0; ks < 4; ks++) {
            const uint32_t ko = (uint32_t)(ks * 16 * 2);
            uint32_t a0[4], a1[4];
            ldsm_x4(a0, Asl + a_lane + ko + (uint32_t)(warpM * SH * 2));
            ldsm_x4(a1, Asl + a_lane + ko + (uint32_t)((warpM + 16) * SH * 2));
#pragma unroll
            for (int p = 0; p < 4; p++) {
                uint32_t b[4];
                ldsm_x4(b, Bsl + b_lane + ko + (uint32_t)((warpN + p * 16) * SH * 2));
                mma_f16(acc[0][2 * p],     a0, b[0], b[1]);
                mma_f16(acc[1][2 * p],     a1, b[0], b[1]);
                mma_f16(acc[0][2 * p + 1], a0, b[2], b[3]);
                mma_f16(acc[1][2 * p + 1], a1, b[2], b[3]);
            }
        }
    }

    // epilogue
    const int g = lane >> 2, t4 = lane & 3;
#pragma unroll
    for (int mt = 0; mt < 2; mt++)
#pragma unroll
        for (int nt = 0; nt < 8; nt++) {
            const int col = n0 + warpN + nt * 8 + 2 * t4;
            const float b0v = __ldg(&g_bias[col]);
            const float b1v = __ldg(&g_bias[col + 1]);
            const int row0 = m0 + warpM + mt * 16 + g;
            if (row0 < N_NODES)
                *reinterpret_cast<float2*>(&out[(size_t)row0 * COUT + col]) =
                    make_float2(acc[mt][nt][0] + b0v, acc[mt][nt][1] + b1v);
            const int row1 = row0 + 8;
            if (row1 < N_NODES)
                *reinterpret_cast<float2*>(&out[(size_t)row1 * COUT + col]) =
                    make_float2(acc[mt][nt][2] + b0v, acc[mt][nt][3] + b1v);
        }
}

// ---------------------------------------------------------------------------
extern "C" void kernel_launch(void* const* d_in, const int* in_sizes, int n_in,
                              void* d_out, int out_size) {
    const float* x  = (const float*)d_in[0];
    const float* nx = (const float*)d_in[1];
    const float* Wl = (const float*)d_in[2];
    const float* bl = (const float*)d_in[3];
    const float* Wr = (const float*)d_in[4];
    const float* br = (const float*)d_in[5];
    float* out = (float*)d_out;

    convert_kernel<<<COUT + XCONV_BLKS, 256>>>(x, Wl, bl, Wr, br);
    agg_kernel<<<N_NODES, 128>>>(nx);

    const int smem_bytes = NST * 2 * STG_H * (int)sizeof(__half);  // 110592
    cudaFuncSetAttribute(gemm_kernel,
                         cudaFuncAttributeMaxDynamicSharedMemorySize, smem_bytes);

    // PDL launch: gemm may start while agg drains; it syncs before reading aggh.
    cudaLaunchConfig_t cfg = {};
    cfg.gridDim  = dim3((N_NODES + TM - 1) / TM, COUT / TN, 1);    // 157 x 4
    cfg.blockDim = dim3(256, 1, 1);
    cfg.dynamicSmemBytes = smem_bytes;
    cfg.stream = 0;
    cudaLaunchAttribute attrs[1];
    attrs[0].id = cudaLaunchAttributeProgrammaticStreamSerialization;
    attrs[0].val.programmaticStreamSerializationAllowed = 1;
    cfg.attrs = attrs;
    cfg.numAttrs = 1;
    cudaLaunchKernelEx(&cfg, gemm_kernel, out);
}